// round 1
// baseline (speedup 1.0000x reference)
#include <cuda_runtime.h>
#include <cuda_fp16.h>
#include <math.h>

// Problem constants
#define kB 2
#define kD 32
#define kC 64
#define kH 72
#define kW 136
#define kHW (kH * kW)              // 9792
#define kCHW (kC * kHW)            // 626688
#define kBCHW (kB * kCHW)          // 1253376
#define kBDHW (kB * kD * kHW)      // 626688

// Packed lookup features: g_packed[b][c][y][x] = half2( f[b,c,y,x], f[b,c,y,x+1] )
// One 4B load yields both x-corners of a bilinear row.
__device__ __half2 g_packed[kBCHW];

__global__ void pack_kernel(const float* __restrict__ lookup) {
    int idx = blockIdx.x * blockDim.x + threadIdx.x;
    if (idx >= kBCHW) return;
    int x = idx % kW;
    float a = lookup[idx];
    float b = (x + 1 < kW) ? lookup[idx + 1] : a;  // clamp; never used with weight>0
    g_packed[idx] = __floats2half2_rn(a, b);
}

__global__ __launch_bounds__(512)
void cv_kernel(const float* __restrict__ cur,
               const float* __restrict__ prior,
               const float* __restrict__ sfac,
               const float* __restrict__ theta,
               const float* __restrict__ angle,
               const float* __restrict__ pose,
               const float* __restrict__ intr,
               const float* __restrict__ dist,
               float* __restrict__ out) {
    __shared__ float cur_s[kC][32];   // current_feats for this (b,h,w-tile)
    __shared__ float red[kD][32];     // per-depth cost, for max reduction

    const int tx  = threadIdx.x;          // w within tile
    const int tyb = threadIdx.y;          // 0..15, covers d = tyb and tyb+16
    const int b   = blockIdx.z;
    const int h   = blockIdx.y;
    const int w   = blockIdx.x * 32 + tx;
    const bool wvalid = (w < kW);
    const int pix = h * kW + w;

    // Stage current_feats[b, :, h, wtile] into smem (coalesced over w)
    for (int c = tyb; c < kC; c += 16) {
        cur_s[c][tx] = wvalid ? cur[(size_t)(b * kC + c) * kHW + pix] : 0.f;
    }
    __syncthreads();

    // ---- per-pixel (depth-independent) quantities ----
    float rx = 0.f, ry = 0.f, rz = 0.f, t0 = 0.f, t1 = 0.f, t2c = 0.f;
    float fx = 0.f, fy = 0.f, cx = 0.f, cy = 0.f;
    float k1 = 0.f, k2 = 0.f, k3 = 0.f, k4 = 0.f;
    float inv_smin = 0.f, inv_smax = 0.f;
    bool pix_in_mask = false;

    if (wvalid) {
        float pd = prior[b * kHW + pix];
        float sf = sfac[pix];
        float th_l = theta[b * kHW + pix];
        float an   = angle[b * kHW + pix];
        float st, ct, sa, ca;
        sincosf(th_l, &st, &ct);
        sincosf(an, &sa, &ca);
        float dx = st * ca, dy = st * sa, dz = ct;

        const float* P = pose + b * 16;
        rx = P[0] * dx + P[1] * dy + P[2] * dz;
        ry = P[4] * dx + P[5] * dy + P[6] * dz;
        rz = P[8] * dx + P[9] * dy + P[10] * dz;
        t0 = P[3]; t1 = P[7]; t2c = P[11];

        fx = intr[b * 9 + 0]; fy = intr[b * 9 + 4];
        cx = intr[b * 9 + 2]; cy = intr[b * 9 + 5];
        k1 = dist[b * 4 + 0]; k2 = dist[b * 4 + 1];
        k3 = dist[b * 4 + 2]; k4 = dist[b * 4 + 3];

        float onesf = 1.f + sf;
        float smin = pd / onesf;
        float smax = pd * onesf;
        inv_smin = 1.f / smin;
        inv_smax = 1.f / smax;

        pix_in_mask = (h >= 2) && (h < kH - 2) && (w >= 2) && (w < kW - 2);
    }

    float costv[2];
    float missv[2];

    #pragma unroll 1
    for (int dd = 0; dd < 2; dd++) {
        const int d = tyb + 16 * dd;
        float diffs = 0.f;

        if (wvalid && pix_in_mask) {
            float itv = (float)d * (1.f / (float)(kD - 1));
            float depth = 1.f / (inv_smax + (inv_smin - inv_smax) * itv);
            float X = depth * rx + t0;
            float Y = depth * ry + t1;
            float Z = depth * rz + t2c;
            float r = sqrtf(X * X + Y * Y) + 1e-8f;
            float thp = atan2f(r, Z);
            float tt = thp * thp;
            float rd = thp * (1.f + tt * (k1 + tt * (k2 + tt * (k3 + tt * k4))));
            float s = rd / r;
            float u = fx * X * s + cx;
            float v = fy * Y * s + cy;

            if (u >= 2.f && u <= (float)(kW - 2) && v >= 2.f && v <= (float)(kH - 2)) {
                float x0f = floorf(u), y0f = floorf(v);
                int x0 = (int)x0f, y0 = (int)y0f;
                float wx1 = u - x0f, wy1 = v - y0f;
                float wx0 = 1.f - wx1, wy0 = 1.f - wy1;
                float w00 = wx0 * wy0, w01 = wx1 * wy0;
                float w10 = wx0 * wy1, w11 = wx1 * wy1;

                const __half2* __restrict__ pbase =
                    g_packed + (size_t)b * kCHW + y0 * kW + x0;
                float acc = 0.f;
                #pragma unroll 16
                for (int c = 0; c < kC; c++) {
                    __half2 h0 = pbase[c * kHW];        // row y0: (f[x0], f[x0+1])
                    __half2 h1 = pbase[c * kHW + kW];   // row y1
                    float2 a = __half22float2(h0);
                    float2 e = __half22float2(h1);
                    float val = w00 * a.x + w01 * a.y + w10 * e.x + w11 * e.y;
                    acc += fabsf(val - cur_s[c][tx]);
                }
                diffs = acc * (1.f / (float)kC);
            }
        }

        // cost = diffs / (counts + 1e-7), counts = (diffs > 0)
        float cnt = (diffs > 0.f) ? 1.f : 0.f;
        float cost = diffs / (cnt + 1e-7f);
        costv[dd] = cost;
        missv[dd] = (diffs == 0.f) ? 1.f : 0.f;
        red[d][tx] = cost;
    }
    __syncthreads();

    // max over depth (per w column)
    #pragma unroll
    for (int s = 16; s > 0; s >>= 1) {
        if (tyb < s) red[tyb][tx] = fmaxf(red[tyb][tx], red[tyb + s][tx]);
        __syncthreads();
    }
    float maxv = red[0][tx];

    if (wvalid) {
        #pragma unroll
        for (int dd = 0; dd < 2; dd++) {
            const int d = tyb + 16 * dd;
            size_t oidx = (((size_t)b * kD + d) * kH + h) * kW + w;
            bool miss = (missv[dd] != 0.f);
            out[oidx] = miss ? maxv : costv[dd];
            out[kBDHW + oidx] = missv[dd];
        }
    }
}

extern "C" void kernel_launch(void* const* d_in, const int* in_sizes, int n_in,
                              void* d_out, int out_size) {
    const float* cur    = (const float*)d_in[0];  // current_feats [B,C,H,W]
    const float* lookup = (const float*)d_in[1];  // lookup_feats  [B,1,C,H,W]
    const float* prior  = (const float*)d_in[2];  // prior_depth   [B,1,H,W]
    const float* sfac   = (const float*)d_in[3];  // scale_facs    [H,W]
    const float* theta  = (const float*)d_in[4];  // theta_lut     [B,H,W]
    const float* angle  = (const float*)d_in[5];  // angle_lut     [B,H,W]
    const float* pose   = (const float*)d_in[6];  // lookup_poses  [B,1,4,4]
    const float* intr   = (const float*)d_in[7];  // intrinsics    [B,3,3]
    const float* dist   = (const float*)d_in[8];  // distortion    [B,4]
    float* out = (float*)d_out;                   // [2, B, D, H, W]

    pack_kernel<<<(kBCHW + 255) / 256, 256>>>(lookup);

    dim3 grid((kW + 31) / 32, kH, kB);
    dim3 block(32, 16);
    cv_kernel<<<grid, block>>>(cur, prior, sfac, theta, angle, pose, intr, dist, out);
}

// round 4
// speedup vs baseline: 2.9779x; 2.9779x over previous
#include <cuda_runtime.h>
#include <cuda_fp16.h>
#include <math.h>

#define kB 2
#define kD 32
#define kC 64
#define kC2 32                     // half2 channel-pairs per texel
#define kCV4 8                     // float4 (16B) chunks per texel
#define kH 72
#define kW 136
#define kHW (kH * kW)              // 9792
#define kNPIX (kB * kHW)           // 19584
#define kBDHW (kB * kD * kHW)      // 626688
#define FULL 0xffffffffu

// Channel-innermost texel layout: [b][pix][c], 128B per texel.
// float4 type guarantees 16-byte alignment for LDG.128.
__device__ float4 g_look[(size_t)kNPIX * kCV4];
__device__ float4 g_cur[(size_t)kNPIX * kCV4];

// Transpose [C][HW] float -> [HW][C2] half2 (channel pairs innermost).
__global__ __launch_bounds__(512)
void pack_kernel(const float* __restrict__ src, int which) {
    __shared__ float s[kC][33];
    __half2* __restrict__ dst =
        reinterpret_cast<__half2*>(which ? g_cur : g_look);
    const int b = blockIdx.y;
    const int pix0 = blockIdx.x * 32;
    const int tx = threadIdx.x, ty = threadIdx.y;
    const float* sb = src + (size_t)b * kC * kHW + pix0;
    for (int c = ty; c < kC; c += 16)
        s[c][tx] = sb[(size_t)c * kHW + tx];
    __syncthreads();
    for (int p = ty; p < 32; p += 16) {
        __half2 v = __floats2half2_rn(s[2 * tx][p], s[2 * tx + 1][p]);
        dst[((size_t)b * kHW + pix0 + p) * kC2 + tx] = v;
    }
}

__global__ __launch_bounds__(256)
void cv_kernel(const float* __restrict__ prior,
               const float* __restrict__ sfac,
               const float* __restrict__ theta,
               const float* __restrict__ angle,
               const float* __restrict__ pose,
               const float* __restrict__ intr,
               const float* __restrict__ dist,
               float* __restrict__ out) {
    __shared__ float cost_s[kD][9];
    __shared__ float miss_s[kD][9];

    const int tid = threadIdx.x;
    const int wp = tid >> 5;      // warp in block = pixel offset (8 pixels/block)
    const int lane = tid & 31;
    const int q = lane & 7;       // 16B channel chunk within 128B texel

    const int gp0 = blockIdx.x * 8;   // 8 consecutive pixels (kW%8==0: same row)
    const int b = gp0 / kHW;
    const int pix0 = gp0 - b * kHW;
    const int h = pix0 / kW;
    const int w0 = pix0 - h * kW;

    const int pix = pix0 + wp;
    const int w = w0 + wp;

    // ---- per-pixel setup (lane-redundant; loads broadcast) ----
    float pd = prior[b * kHW + pix];
    float sf = sfac[pix];
    float th = theta[b * kHW + pix];
    float an = angle[b * kHW + pix];
    float st, ct, sa, ca;
    sincosf(th, &st, &ct);
    sincosf(an, &sa, &ca);
    float dxv = st * ca, dyv = st * sa, dzv = ct;
    const float* P = pose + b * 16;
    float rx = P[0] * dxv + P[1] * dyv + P[2] * dzv;
    float ry = P[4] * dxv + P[5] * dyv + P[6] * dzv;
    float rz = P[8] * dxv + P[9] * dyv + P[10] * dzv;
    float t0 = P[3], t1 = P[7], t2 = P[11];
    float fx = intr[b * 9 + 0], fy = intr[b * 9 + 4];
    float cx = intr[b * 9 + 2], cy = intr[b * 9 + 5];
    float k1 = dist[b * 4 + 0], k2 = dist[b * 4 + 1];
    float k3 = dist[b * 4 + 2], k4 = dist[b * 4 + 3];
    float onesf = 1.f + sf;
    float inv_smin = onesf / pd;
    float inv_smax = 1.f / (pd * onesf);
    bool inmask = (h >= 2) && (h < kH - 2) && (w >= 2) && (w < kW - 2);

    // ---- per-lane depth d = lane: projection in parallel ----
    float itv = (float)lane * (1.f / 31.f);
    float depth = 1.f / (inv_smax + (inv_smin - inv_smax) * itv);
    float X = depth * rx + t0, Y = depth * ry + t1, Z = depth * rz + t2;
    float r = sqrtf(X * X + Y * Y) + 1e-8f;
    float thp = atan2f(r, Z);
    float tt = thp * thp;
    float rdv = thp * (1.f + tt * (k1 + tt * (k2 + tt * (k3 + tt * k4))));
    float scl = rdv / r;
    float u = fx * X * scl + cx;
    float v = fy * Y * scl + cy;
    bool ok = inmask && (u >= 2.f) && (u <= (float)(kW - 2)) &&
              (v >= 2.f) && (v <= (float)(kH - 2));
    unsigned okmask = __ballot_sync(FULL, ok);

    float x0f = floorf(u), y0f = floorf(v);
    float wx1 = u - x0f, wy1 = v - y0f;
    int off = ((int)y0f * kW + (int)x0f) * kCV4;  // float4-unit offset in batch

    // cur channels for this lane's chunk (reused across all depths)
    float curf[8];
    {
        const float4* cp = g_cur + ((size_t)b * kHW + pix) * kCV4;
        float4 cc = cp[q];
        const __half2* ch = reinterpret_cast<const __half2*>(&cc);
#pragma unroll
        for (int k = 0; k < 4; k++) {
            float2 f = __half22float2(ch[k]);
            curf[2 * k] = f.x;
            curf[2 * k + 1] = f.y;
        }
    }

    const float4* lbase = g_look + (size_t)b * kHW * kCV4;
    float mydiff = 0.f;

    if (okmask) {
#pragma unroll
        for (int i = 0; i < 8; i++) {
            const int src = (lane & 24) | i;     // this subgroup's depth lane
            float wxi = __shfl_sync(FULL, wx1, src);
            float wyi = __shfl_sync(FULL, wy1, src);
            int offi = __shfl_sync(FULL, off, src);
            float acc = 0.f;
            if ((okmask >> src) & 1u) {
                const float4* p00 = lbase + offi;
                float4 A = p00[q];                     // (y0 , x0 )
                float4 Bc = p00[q + kCV4];             // (y0 , x0+1)
                float4 Cc = p00[q + kW * kCV4];        // (y0+1, x0 )
                float4 Dc = p00[q + kW * kCV4 + kCV4]; // (y0+1, x0+1)
                float w11 = wxi * wyi;
                float w01 = wxi - w11;                 // wx*(1-wy)
                float w10 = wyi - w11;                 // (1-wx)*wy
                float w00 = 1.f - wxi - w10;           // (1-wx)*(1-wy)
                __half2 W00 = __float2half2_rn(w00);
                __half2 W01 = __float2half2_rn(w01);
                __half2 W10 = __float2half2_rn(w10);
                __half2 W11 = __float2half2_rn(w11);
                const __half2* Ah = reinterpret_cast<const __half2*>(&A);
                const __half2* Bh = reinterpret_cast<const __half2*>(&Bc);
                const __half2* Ch = reinterpret_cast<const __half2*>(&Cc);
                const __half2* Dh = reinterpret_cast<const __half2*>(&Dc);
#pragma unroll
                for (int k = 0; k < 4; k++) {
                    __half2 val = __hfma2(Ah[k], W00,
                                  __hfma2(Bh[k], W01,
                                  __hfma2(Ch[k], W10,
                                  __hmul2(Dh[k], W11))));
                    float2 f = __half22float2(val);
                    acc += fabsf(f.x - curf[2 * k]) + fabsf(f.y - curf[2 * k + 1]);
                }
            }
            // sum across the 8 lanes of this depth's subgroup
            acc += __shfl_xor_sync(FULL, acc, 4);
            acc += __shfl_xor_sync(FULL, acc, 2);
            acc += __shfl_xor_sync(FULL, acc, 1);
            if (q == i) mydiff = acc * (1.f / (float)kC);
        }
    }

    // cost / missing / max-over-depth (lane = depth)
    float cnt = (mydiff > 0.f) ? 1.f : 0.f;
    float cost = mydiff / (cnt + 1e-7f);
    float miss = (mydiff == 0.f) ? 1.f : 0.f;
    float maxv = cost;
#pragma unroll
    for (int o = 16; o > 0; o >>= 1)
        maxv = fmaxf(maxv, __shfl_xor_sync(FULL, maxv, o));
    float outc = (miss != 0.f) ? maxv : cost;

    cost_s[lane][wp] = outc;
    miss_s[lane][wp] = miss;
    __syncthreads();

    // coalesced stores: 8 consecutive w per depth row
    const int d = tid >> 3, p = tid & 7;
    size_t oidx = (((size_t)b * kD + d) * kH + h) * kW + (w0 + p);
    out[oidx] = cost_s[d][p];
    out[kBDHW + oidx] = miss_s[d][p];
}

extern "C" void kernel_launch(void* const* d_in, const int* in_sizes, int n_in,
                              void* d_out, int out_size) {
    const float* cur    = (const float*)d_in[0];  // current_feats [B,C,H,W]
    const float* lookup = (const float*)d_in[1];  // lookup_feats  [B,1,C,H,W]
    const float* prior  = (const float*)d_in[2];  // prior_depth   [B,1,H,W]
    const float* sfac   = (const float*)d_in[3];  // scale_facs    [H,W]
    const float* theta  = (const float*)d_in[4];  // theta_lut     [B,H,W]
    const float* angle  = (const float*)d_in[5];  // angle_lut     [B,H,W]
    const float* pose   = (const float*)d_in[6];  // lookup_poses  [B,1,4,4]
    const float* intr   = (const float*)d_in[7];  // intrinsics    [B,3,3]
    const float* dist   = (const float*)d_in[8];  // distortion    [B,4]
    float* out = (float*)d_out;                   // [2, B, D, H, W]

    dim3 pgrid(kHW / 32, kB);
    dim3 pblock(32, 16);
    pack_kernel<<<pgrid, pblock>>>(lookup, 0);
    pack_kernel<<<pgrid, pblock>>>(cur, 1);

    cv_kernel<<<kNPIX / 8, 256>>>(prior, sfac, theta, angle, pose, intr, dist, out);
}

// round 5
// speedup vs baseline: 3.3268x; 1.1172x over previous
#include <cuda_runtime.h>
#include <cuda_fp16.h>
#include <math.h>

#define kB 2
#define kD 32
#define kC 64
#define kC2 32                     // half2 channel-pairs per texel
#define kCV4 8                     // float4 (16B) chunks per texel
#define kH 72
#define kW 136
#define kHW (kH * kW)              // 9792
#define kNPIX (kB * kHW)           // 19584
#define kBDHW (kB * kD * kHW)      // 626688
#define FULL 0xffffffffu
#define PACK_PIX 96                // pixels per pack block (9792 = 102*96)

// Channel-innermost lookup texels: [b][pix][c], 128B per texel.
// float4 type guarantees 16-byte alignment for LDG.128/STG.128.
__device__ float4 g_look[(size_t)kNPIX * kCV4];

// Transpose lookup [C][HW] float -> [HW][C2] half2 (channels innermost).
__global__ __launch_bounds__(256)
void pack_kernel(const float* __restrict__ src) {
    __shared__ float s[kC][PACK_PIX + 1];   // +1 pad: conflict-light reads
    const int b = blockIdx.y;
    const int pix0 = blockIdx.x * PACK_PIX;
    const int t = threadIdx.x;
    const float* sb = src + (size_t)b * kC * kHW + pix0;

    // Load 64ch x 24 float4 = 1536 float4, 6 per thread, coalesced.
#pragma unroll
    for (int i = 0; i < 6; i++) {
        int e = t + i * 256;
        int c = e / 24, p4 = e % 24;
        float4 v = *reinterpret_cast<const float4*>(sb + (size_t)c * kHW + p4 * 4);
        s[c][p4 * 4 + 0] = v.x;
        s[c][p4 * 4 + 1] = v.y;
        s[c][p4 * 4 + 2] = v.z;
        s[c][p4 * 4 + 3] = v.w;
    }
    __syncthreads();

    // Emit 96 pix x 8 float4 (each = 8 channels as 4 half2), coalesced stores.
    float4* dst = g_look + ((size_t)b * kHW + pix0) * kCV4;
#pragma unroll
    for (int i = 0; i < 3; i++) {
        int e = t + i * 256;
        int pix = e >> 3, q = e & 7;
        float4 o;
        __half2* oh = reinterpret_cast<__half2*>(&o);
#pragma unroll
        for (int k = 0; k < 4; k++)
            oh[k] = __floats2half2_rn(s[8 * q + 2 * k][pix],
                                      s[8 * q + 2 * k + 1][pix]);
        dst[e] = o;
    }
}

__global__ __launch_bounds__(256)
void cv_kernel(const float* __restrict__ cur,
               const float* __restrict__ prior,
               const float* __restrict__ sfac,
               const float* __restrict__ theta,
               const float* __restrict__ angle,
               const float* __restrict__ pose,
               const float* __restrict__ intr,
               const float* __restrict__ dist,
               float* __restrict__ out) {
    __shared__ float cur_s[8][68];    // [pixel][channel], stride 68: no write conflicts
    __shared__ float cost_s[kD][9];
    __shared__ float miss_s[kD][9];

    const int tid = threadIdx.x;
    const int wp = tid >> 5;      // warp in block = pixel offset (8 pixels/block)
    const int lane = tid & 31;
    const int q = lane & 7;       // 16B channel chunk within 128B texel

    const int gp0 = blockIdx.x * 8;   // 8 consecutive pixels (kW%8==0: same row)
    const int b = gp0 / kHW;
    const int pix0 = gp0 - b * kHW;
    const int h = pix0 / kW;
    const int w0 = pix0 - h * kW;

    const int pix = pix0 + wp;
    const int w = w0 + wp;

    // Stage current_feats[b, :, h, w0..w0+7] (coalesced 32B runs per 8 lanes)
    {
        const float* curb = cur + (size_t)b * kC * kHW + pix0;
#pragma unroll
        for (int e = tid; e < 512; e += 256) {
            int c = e >> 3, p = e & 7;
            cur_s[p][c] = curb[(size_t)c * kHW + p];
        }
    }
    __syncthreads();

    // ---- per-pixel setup (lane-redundant; loads broadcast) ----
    float pd = prior[b * kHW + pix];
    float sf = sfac[pix];
    float th = theta[b * kHW + pix];
    float an = angle[b * kHW + pix];
    float st, ct, sa, ca;
    sincosf(th, &st, &ct);
    sincosf(an, &sa, &ca);
    float dxv = st * ca, dyv = st * sa, dzv = ct;
    const float* P = pose + b * 16;
    float rx = P[0] * dxv + P[1] * dyv + P[2] * dzv;
    float ry = P[4] * dxv + P[5] * dyv + P[6] * dzv;
    float rz = P[8] * dxv + P[9] * dyv + P[10] * dzv;
    float t0 = P[3], t1 = P[7], t2 = P[11];
    float fx = intr[b * 9 + 0], fy = intr[b * 9 + 4];
    float cx = intr[b * 9 + 2], cy = intr[b * 9 + 5];
    float k1 = dist[b * 4 + 0], k2 = dist[b * 4 + 1];
    float k3 = dist[b * 4 + 2], k4 = dist[b * 4 + 3];
    float onesf = 1.f + sf;
    float inv_smin = onesf / pd;
    float inv_smax = 1.f / (pd * onesf);
    bool inmask = (h >= 2) && (h < kH - 2) && (w >= 2) && (w < kW - 2);

    // ---- per-lane depth d = lane: projection in parallel ----
    float itv = (float)lane * (1.f / 31.f);
    float depth = 1.f / (inv_smax + (inv_smin - inv_smax) * itv);
    float X = depth * rx + t0, Y = depth * ry + t1, Z = depth * rz + t2;
    float r = sqrtf(X * X + Y * Y) + 1e-8f;
    float thp = atan2f(r, Z);
    float tt = thp * thp;
    float rdv = thp * (1.f + tt * (k1 + tt * (k2 + tt * (k3 + tt * k4))));
    float scl = rdv / r;
    float u = fx * X * scl + cx;
    float v = fy * Y * scl + cy;
    bool ok = inmask && (u >= 2.f) && (u <= (float)(kW - 2)) &&
              (v >= 2.f) && (v <= (float)(kH - 2));
    unsigned okmask = __ballot_sync(FULL, ok);

    float x0f = floorf(u), y0f = floorf(v);
    float wx1 = u - x0f, wy1 = v - y0f;
    int off = ((int)y0f * kW + (int)x0f) * kCV4;  // float4-unit offset in batch

    // cur channels for this lane's chunk (fp32, from smem; reused all depths)
    float curf[8];
#pragma unroll
    for (int k = 0; k < 8; k++) curf[k] = cur_s[wp][8 * q + k];

    const float4* lbase = g_look + (size_t)b * kHW * kCV4;
    float mydiff = 0.f;

    if (okmask) {
#pragma unroll
        for (int i = 0; i < 8; i++) {
            const int src = (lane & 24) | i;     // this subgroup's depth lane
            float wxi = __shfl_sync(FULL, wx1, src);
            float wyi = __shfl_sync(FULL, wy1, src);
            int offi = __shfl_sync(FULL, off, src);
            float acc = 0.f;
            if ((okmask >> src) & 1u) {
                const float4* p00 = lbase + offi;
                float4 A = p00[q];                     // (y0 , x0 )
                float4 Bc = p00[q + kCV4];             // (y0 , x0+1)
                float4 Cc = p00[q + kW * kCV4];        // (y0+1, x0 )
                float4 Dc = p00[q + kW * kCV4 + kCV4]; // (y0+1, x0+1)
                float w11 = wxi * wyi;
                float w01 = wxi - w11;                 // wx*(1-wy)
                float w10 = wyi - w11;                 // (1-wx)*wy
                float w00 = 1.f - wxi - w10;           // (1-wx)*(1-wy)
                __half2 W00 = __float2half2_rn(w00);
                __half2 W01 = __float2half2_rn(w01);
                __half2 W10 = __float2half2_rn(w10);
                __half2 W11 = __float2half2_rn(w11);
                const __half2* Ah = reinterpret_cast<const __half2*>(&A);
                const __half2* Bh = reinterpret_cast<const __half2*>(&Bc);
                const __half2* Ch = reinterpret_cast<const __half2*>(&Cc);
                const __half2* Dh = reinterpret_cast<const __half2*>(&Dc);
#pragma unroll
                for (int k = 0; k < 4; k++) {
                    __half2 val = __hfma2(Ah[k], W00,
                                  __hfma2(Bh[k], W01,
                                  __hfma2(Ch[k], W10,
                                  __hmul2(Dh[k], W11))));
                    float2 f = __half22float2(val);
                    acc += fabsf(f.x - curf[2 * k]) + fabsf(f.y - curf[2 * k + 1]);
                }
            }
            // sum across the 8 lanes of this depth's subgroup
            acc += __shfl_xor_sync(FULL, acc, 4);
            acc += __shfl_xor_sync(FULL, acc, 2);
            acc += __shfl_xor_sync(FULL, acc, 1);
            if (q == i) mydiff = acc * (1.f / (float)kC);
        }
    }

    // cost / missing / max-over-depth (lane = depth)
    float cnt = (mydiff > 0.f) ? 1.f : 0.f;
    float cost = mydiff / (cnt + 1e-7f);
    float miss = (mydiff == 0.f) ? 1.f : 0.f;
    float maxv = cost;
#pragma unroll
    for (int o = 16; o > 0; o >>= 1)
        maxv = fmaxf(maxv, __shfl_xor_sync(FULL, maxv, o));
    float outc = (miss != 0.f) ? maxv : cost;

    cost_s[lane][wp] = outc;
    miss_s[lane][wp] = miss;
    __syncthreads();

    // coalesced stores: 8 consecutive w per depth row
    const int d = tid >> 3, p = tid & 7;
    size_t oidx = (((size_t)b * kD + d) * kH + h) * kW + (w0 + p);
    out[oidx] = cost_s[d][p];
    out[kBDHW + oidx] = miss_s[d][p];
}

extern "C" void kernel_launch(void* const* d_in, const int* in_sizes, int n_in,
                              void* d_out, int out_size) {
    const float* cur    = (const float*)d_in[0];  // current_feats [B,C,H,W]
    const float* lookup = (const float*)d_in[1];  // lookup_feats  [B,1,C,H,W]
    const float* prior  = (const float*)d_in[2];  // prior_depth   [B,1,H,W]
    const float* sfac   = (const float*)d_in[3];  // scale_facs    [H,W]
    const float* theta  = (const float*)d_in[4];  // theta_lut     [B,H,W]
    const float* angle  = (const float*)d_in[5];  // angle_lut     [B,H,W]
    const float* pose   = (const float*)d_in[6];  // lookup_poses  [B,1,4,4]
    const float* intr   = (const float*)d_in[7];  // intrinsics    [B,3,3]
    const float* dist   = (const float*)d_in[8];  // distortion    [B,4]
    float* out = (float*)d_out;                   // [2, B, D, H, W]

    dim3 pgrid(kHW / PACK_PIX, kB);               // (102, 2)
    pack_kernel<<<pgrid, 256>>>(lookup);

    cv_kernel<<<kNPIX / 8, 256>>>(cur, prior, sfac, theta, angle, pose,
                                  intr, dist, out);
}

// round 6
// speedup vs baseline: 3.5784x; 1.0756x over previous
#include <cuda_runtime.h>
#include <cuda_fp16.h>
#include <math.h>

#define kB 2
#define kD 32
#define kC 64
#define kC2 32                     // half2 channel-pairs per texel
#define kCV4 8                     // float4 (16B) chunks per texel
#define kTEXB 128                  // bytes per texel
#define kH 72
#define kW 136
#define kHW (kH * kW)              // 9792
#define kNPIX (kB * kHW)           // 19584
#define kBDHW (kB * kD * kHW)      // 626688
#define FULL 0xffffffffu
#define PACK_PIX 96                // pixels per pack block (9792 = 102*96)

// Channel-innermost lookup texels: [b][pix][c], 128B per texel.
__device__ float4 g_look[(size_t)kNPIX * kCV4];

// Transpose lookup [C][HW] float -> [HW][C2] half2 (channels innermost).
__global__ __launch_bounds__(256)
void pack_kernel(const float* __restrict__ src) {
    __shared__ float s[kC][PACK_PIX + 1];
    const int b = blockIdx.y;
    const int pix0 = blockIdx.x * PACK_PIX;
    const int t = threadIdx.x;
    const float* sb = src + (size_t)b * kC * kHW + pix0;

#pragma unroll
    for (int i = 0; i < 6; i++) {
        int e = t + i * 256;
        int c = e / 24, p4 = e % 24;
        float4 v = *reinterpret_cast<const float4*>(sb + (size_t)c * kHW + p4 * 4);
        s[c][p4 * 4 + 0] = v.x;
        s[c][p4 * 4 + 1] = v.y;
        s[c][p4 * 4 + 2] = v.z;
        s[c][p4 * 4 + 3] = v.w;
    }
    __syncthreads();

    float4* dst = g_look + ((size_t)b * kHW + pix0) * kCV4;
#pragma unroll
    for (int i = 0; i < 3; i++) {
        int e = t + i * 256;
        int pix = e >> 3, q = e & 7;
        float4 o;
        __half2* oh = reinterpret_cast<__half2*>(&o);
#pragma unroll
        for (int k = 0; k < 4; k++)
            oh[k] = __floats2half2_rn(s[8 * q + 2 * k][pix],
                                      s[8 * q + 2 * k + 1][pix]);
        dst[e] = o;
    }
}

__global__ __launch_bounds__(256)
void cv_kernel(const float* __restrict__ cur,
               const float* __restrict__ prior,
               const float* __restrict__ sfac,
               const float* __restrict__ theta,
               const float* __restrict__ angle,
               const float* __restrict__ pose,
               const float* __restrict__ intr,
               const float* __restrict__ dist,
               float* __restrict__ out) {
    __shared__ __half2 cur_h[8][32];  // [pixel][channel-pair]
    __shared__ float cost_s[kD][9];
    __shared__ float miss_s[kD][9];

    const int tid = threadIdx.x;
    const int wp = tid >> 5;      // warp in block = pixel offset (8 pixels/block)
    const int lane = tid & 31;
    const int q = lane & 7;       // 16B channel chunk within 128B texel

    const int gp0 = blockIdx.x * 8;   // 8 consecutive pixels (kW%8==0: same row)
    const int b = gp0 / kHW;
    const int pix0 = gp0 - b * kHW;
    const int h = pix0 / kW;
    const int w0 = pix0 - h * kW;

    const int pix = pix0 + wp;
    const int w = w0 + wp;

    // Stage current_feats[b, :, h, w0..w0+7] as half2 (convert once)
    {
        const float* curb = cur + (size_t)b * kC * kHW + pix0;
        int p = tid & 7, c2 = tid >> 3;           // 256 threads = 8pix x 32c2
        float a = curb[(size_t)(2 * c2) * kHW + p];
        float bb = curb[(size_t)(2 * c2 + 1) * kHW + p];
        cur_h[p][c2] = __floats2half2_rn(a, bb);
    }
    __syncthreads();

    // ---- per-pixel setup (lane-redundant; loads broadcast) ----
    float pd = prior[b * kHW + pix];
    float sf = sfac[pix];
    float th = theta[b * kHW + pix];
    float an = angle[b * kHW + pix];
    float st, ct, sa, ca;
    sincosf(th, &st, &ct);
    sincosf(an, &sa, &ca);
    float dxv = st * ca, dyv = st * sa, dzv = ct;
    const float* P = pose + b * 16;
    float rx = P[0] * dxv + P[1] * dyv + P[2] * dzv;
    float ry = P[4] * dxv + P[5] * dyv + P[6] * dzv;
    float rz = P[8] * dxv + P[9] * dyv + P[10] * dzv;
    float t0 = P[3], t1 = P[7], t2 = P[11];
    float fx = intr[b * 9 + 0], fy = intr[b * 9 + 4];
    float cx = intr[b * 9 + 2], cy = intr[b * 9 + 5];
    float k1 = dist[b * 4 + 0], k2 = dist[b * 4 + 1];
    float k3 = dist[b * 4 + 2], k4 = dist[b * 4 + 3];
    float onesf = 1.f + sf;
    float inv_smin = onesf / pd;
    float inv_smax = 1.f / (pd * onesf);
    bool inmask = (h >= 2) && (h < kH - 2) && (w >= 2) && (w < kW - 2);

    // ---- per-lane depth d = lane: projection in parallel ----
    float itv = (float)lane * (1.f / 31.f);
    float depth = 1.f / (inv_smax + (inv_smin - inv_smax) * itv);
    float X = depth * rx + t0, Y = depth * ry + t1, Z = depth * rz + t2;
    float r = sqrtf(X * X + Y * Y) + 1e-8f;
    float thp = atan2f(r, Z);
    float tt = thp * thp;
    float rdv = thp * (1.f + tt * (k1 + tt * (k2 + tt * (k3 + tt * k4))));
    float scl = rdv / r;
    float u = fx * X * scl + cx;
    float v = fy * Y * scl + cy;
    bool ok = inmask && (u >= 2.f) && (u <= (float)(kW - 2)) &&
              (v >= 2.f) && (v <= (float)(kH - 2));
    unsigned okmask = __ballot_sync(FULL, ok);

    float x0f = floorf(u), y0f = floorf(v);
    float wx1 = u - x0f, wy1 = v - y0f;
    int offB = ((int)y0f * kW + (int)x0f) * kTEXB;  // byte offset within batch

    // cur channel-pairs for this lane's chunk (half2, reused for all depths)
    __half2 curh[4];
#pragma unroll
    for (int k = 0; k < 4; k++) curh[k] = cur_h[wp][4 * q + k];

    // base for this lane's 16B chunk within a texel
    const char* lbase = reinterpret_cast<const char*>(g_look) +
                        (size_t)b * kHW * kTEXB + q * 16;
    float mydiff = 0.f;

    if (okmask) {
#pragma unroll
        for (int i = 0; i < 8; i++) {
            const int src = (lane & 24) | i;     // this subgroup's depth lane
            float wxi = __shfl_sync(FULL, wx1, src);
            float wyi = __shfl_sync(FULL, wy1, src);
            int offi = __shfl_sync(FULL, offB, src);
            float acc = 0.f;
            if ((okmask >> src) & 1u) {
                const char* p00 = lbase + offi;
                // 4 corners at immediate offsets from one pointer
                float4 A = *reinterpret_cast<const float4*>(p00);
                float4 Bc = *reinterpret_cast<const float4*>(p00 + kTEXB);
                float4 Cc = *reinterpret_cast<const float4*>(p00 + kW * kTEXB);
                float4 Dc = *reinterpret_cast<const float4*>(p00 + kW * kTEXB + kTEXB);
                float w11 = wxi * wyi;
                float w01 = wxi - w11;
                float w10 = wyi - w11;
                float w00 = 1.f - wxi - w10;
                __half2 W00 = __float2half2_rn(w00);
                __half2 W01 = __float2half2_rn(w01);
                __half2 W10 = __float2half2_rn(w10);
                __half2 W11 = __float2half2_rn(w11);
                const __half2* Ah = reinterpret_cast<const __half2*>(&A);
                const __half2* Bh = reinterpret_cast<const __half2*>(&Bc);
                const __half2* Ch = reinterpret_cast<const __half2*>(&Cc);
                const __half2* Dh = reinterpret_cast<const __half2*>(&Dc);
                __half2 acc2 = __float2half2_rn(0.f);
#pragma unroll
                for (int k = 0; k < 4; k++) {
                    __half2 val = __hfma2(Ah[k], W00,
                                  __hfma2(Bh[k], W01,
                                  __hfma2(Ch[k], W10,
                                  __hmul2(Dh[k], W11))));
                    acc2 = __hadd2(acc2, __habs2(__hsub2(val, curh[k])));
                }
                float2 f = __half22float2(acc2);   // fp32 before cross-lane sum
                acc = f.x + f.y;
            }
            // sum across the 8 lanes of this depth's subgroup
            acc += __shfl_xor_sync(FULL, acc, 4);
            acc += __shfl_xor_sync(FULL, acc, 2);
            acc += __shfl_xor_sync(FULL, acc, 1);
            if (q == i) mydiff = acc * (1.f / (float)kC);
        }
    }

    // cost / missing / max-over-depth (lane = depth)
    float cnt = (mydiff > 0.f) ? 1.f : 0.f;
    float cost = mydiff / (cnt + 1e-7f);
    float miss = (mydiff == 0.f) ? 1.f : 0.f;
    float maxv = cost;
#pragma unroll
    for (int o = 16; o > 0; o >>= 1)
        maxv = fmaxf(maxv, __shfl_xor_sync(FULL, maxv, o));
    float outc = (miss != 0.f) ? maxv : cost;

    cost_s[lane][wp] = outc;
    miss_s[lane][wp] = miss;
    __syncthreads();

    // coalesced stores: 8 consecutive w per depth row
    const int d = tid >> 3, p = tid & 7;
    size_t oidx = (((size_t)b * kD + d) * kH + h) * kW + (w0 + p);
    out[oidx] = cost_s[d][p];
    out[kBDHW + oidx] = miss_s[d][p];
}

extern "C" void kernel_launch(void* const* d_in, const int* in_sizes, int n_in,
                              void* d_out, int out_size) {
    const float* cur    = (const float*)d_in[0];  // current_feats [B,C,H,W]
    const float* lookup = (const float*)d_in[1];  // lookup_feats  [B,1,C,H,W]
    const float* prior  = (const float*)d_in[2];  // prior_depth   [B,1,H,W]
    const float* sfac   = (const float*)d_in[3];  // scale_facs    [H,W]
    const float* theta  = (const float*)d_in[4];  // theta_lut     [B,H,W]
    const float* angle  = (const float*)d_in[5];  // angle_lut     [B,H,W]
    const float* pose   = (const float*)d_in[6];  // lookup_poses  [B,1,4,4]
    const float* intr   = (const float*)d_in[7];  // intrinsics    [B,3,3]
    const float* dist   = (const float*)d_in[8];  // distortion    [B,4]
    float* out = (float*)d_out;                   // [2, B, D, H, W]

    dim3 pgrid(kHW / PACK_PIX, kB);               // (102, 2)
    pack_kernel<<<pgrid, 256>>>(lookup);

    cv_kernel<<<kNPIX / 8, 256>>>(cur, prior, sfac, theta, angle, pose,
                                  intr, dist, out);
}

// round 8
// speedup vs baseline: 3.6190x; 1.0113x over previous
#include <cuda_runtime.h>
#include <cuda_fp16.h>
#include <math.h>

#define kB 2
#define kD 32
#define kC 64
#define kCV4 8                     // float4 (16B) chunks per texel
#define kTEXB 128                  // bytes per texel
#define kH 72
#define kW 136
#define kHW (kH * kW)              // 9792
#define kNPIX (kB * kHW)           // 19584
#define kBDHW (kB * kD * kHW)      // 626688
#define FULL 0xffffffffu
#define PACK_PIX 96                // pixels per pack block (9792 = 102*96)

// Channel-innermost lookup texels: [b][pix][c], 128B per texel.
__device__ float4 g_look[(size_t)kNPIX * kCV4];

// Transpose lookup [C][HW] float -> [HW][C2] half2 (channels innermost).
__global__ __launch_bounds__(256)
void pack_kernel(const float* __restrict__ src) {
    __shared__ float s[kC][PACK_PIX + 1];
    const int b = blockIdx.y;
    const int pix0 = blockIdx.x * PACK_PIX;
    const int t = threadIdx.x;
    const float* sb = src + (size_t)b * kC * kHW + pix0;

#pragma unroll
    for (int i = 0; i < 6; i++) {
        int e = t + i * 256;
        int c = e / 24, p4 = e % 24;
        float4 v = *reinterpret_cast<const float4*>(sb + (size_t)c * kHW + p4 * 4);
        s[c][p4 * 4 + 0] = v.x;
        s[c][p4 * 4 + 1] = v.y;
        s[c][p4 * 4 + 2] = v.z;
        s[c][p4 * 4 + 3] = v.w;
    }
    __syncthreads();

    float4* dst = g_look + ((size_t)b * kHW + pix0) * kCV4;
#pragma unroll
    for (int i = 0; i < 3; i++) {
        int e = t + i * 256;
        int pix = e >> 3, q = e & 7;
        float4 o;
        __half2* oh = reinterpret_cast<__half2*>(&o);
#pragma unroll
        for (int k = 0; k < 4; k++)
            oh[k] = __floats2half2_rn(s[8 * q + 2 * k][pix],
                                      s[8 * q + 2 * k + 1][pix]);
        dst[e] = o;
    }
}

__global__ __launch_bounds__(256)
void cv_kernel(const float* __restrict__ cur,
               const float* __restrict__ prior,
               const float* __restrict__ sfac,
               const float* __restrict__ theta,
               const float* __restrict__ angle,
               const float* __restrict__ pose,
               const float* __restrict__ intr,
               const float* __restrict__ dist,
               float* __restrict__ out) {
    __shared__ __half2 cur_h[8][32];  // [pixel][channel-pair]
    __shared__ float cost_s[kD][9];
    __shared__ float miss_s[kD][9];

    const int tid = threadIdx.x;
    const int wp = tid >> 5;      // warp in block = pixel offset (8 pixels/block)
    const int lane = tid & 31;
    const int q = lane & 7;       // 16B channel chunk within 128B texel

    const int gp0 = blockIdx.x * 8;   // 8 consecutive pixels (kW%8==0: same row)
    const int b = gp0 / kHW;
    const int pix0 = gp0 - b * kHW;
    const int h = pix0 / kW;
    const int w0 = pix0 - h * kW;

    const int pix = pix0 + wp;
    const int w = w0 + wp;

    // Stage current_feats[b, :, h, w0..w0+7] as half2 (convert once)
    {
        const float* curb = cur + (size_t)b * kC * kHW + pix0;
        int p = tid & 7, c2 = tid >> 3;           // 256 threads = 8pix x 32c2
        float a = curb[(size_t)(2 * c2) * kHW + p];
        float bb = curb[(size_t)(2 * c2 + 1) * kHW + p];
        cur_h[p][c2] = __floats2half2_rn(a, bb);
    }
    __syncthreads();

    // ---- per-pixel setup (lane-redundant; loads broadcast) ----
    float pd = prior[b * kHW + pix];
    float sf = sfac[pix];
    float th = theta[b * kHW + pix];
    float an = angle[b * kHW + pix];
    float st, ct, sa, ca;
    sincosf(th, &st, &ct);
    sincosf(an, &sa, &ca);
    float dxv = st * ca, dyv = st * sa, dzv = ct;
    const float* P = pose + b * 16;
    float rx = P[0] * dxv + P[1] * dyv + P[2] * dzv;
    float ry = P[4] * dxv + P[5] * dyv + P[6] * dzv;
    float rz = P[8] * dxv + P[9] * dyv + P[10] * dzv;
    float t0 = P[3], t1 = P[7], t2 = P[11];
    float fx = intr[b * 9 + 0], fy = intr[b * 9 + 4];
    float cx = intr[b * 9 + 2], cy = intr[b * 9 + 5];
    float k1 = dist[b * 4 + 0], k2 = dist[b * 4 + 1];
    float k3 = dist[b * 4 + 2], k4 = dist[b * 4 + 3];
    float onesf = 1.f + sf;
    float inv_smin = onesf / pd;
    float inv_smax = 1.f / (pd * onesf);
    bool inmask = (h >= 2) && (h < kH - 2) && (w >= 2) && (w < kW - 2);

    // ---- per-lane depth d = lane: projection in parallel ----
    float itv = (float)lane * (1.f / 31.f);
    float depth = 1.f / (inv_smax + (inv_smin - inv_smax) * itv);
    float X = depth * rx + t0, Y = depth * ry + t1, Z = depth * rz + t2;
    float r = sqrtf(X * X + Y * Y) + 1e-8f;
    float thp = atan2f(r, Z);
    float tt = thp * thp;
    float rdv = thp * (1.f + tt * (k1 + tt * (k2 + tt * (k3 + tt * k4))));
    float scl = rdv / r;
    float u = fx * X * scl + cx;
    float v = fy * Y * scl + cy;
    bool ok = inmask && (u >= 2.f) && (u <= (float)(kW - 2)) &&
              (v >= 2.f) && (v <= (float)(kH - 2));
    unsigned okmask = __ballot_sync(FULL, ok);

    float x0f = floorf(u), y0f = floorf(v);
    float wx1 = u - x0f, wy1 = v - y0f;
    int offB = ((int)y0f * kW + (int)x0f) * kTEXB;  // byte offset within batch

    // Precompute this lane's (depth's) bilinear weights, packed as 2x half2.
    float w11f = wx1 * wy1;
    float w01f = wx1 - w11f;                // wx*(1-wy)
    float w10f = wy1 - w11f;                // (1-wx)*wy
    float w00f = 1.f - wx1 - w10f;          // (1-wx)*(1-wy)
    __half2 wpackA = __floats2half2_rn(w00f, w01f);
    __half2 wpackB = __floats2half2_rn(w10f, w11f);
    unsigned wAu = *reinterpret_cast<unsigned*>(&wpackA);
    unsigned wBu = *reinterpret_cast<unsigned*>(&wpackB);

    // cur channel-pairs for this lane's chunk (half2, reused for all depths)
    __half2 curh[4];
#pragma unroll
    for (int k = 0; k < 4; k++) curh[k] = cur_h[wp][4 * q + k];

    // base for this lane's 16B chunk within a texel
    const char* lbase = reinterpret_cast<const char*>(g_look) +
                        (size_t)b * kHW * kTEXB + q * 16;
    float mydiff = 0.f;

    if (okmask) {
        float a[8];
#pragma unroll
        for (int i = 0; i < 8; i++) {
            const int src = (lane & 24) | i;     // this subgroup's depth lane
            int offi = __shfl_sync(FULL, offB, src);
            unsigned au = __shfl_sync(FULL, wAu, src);
            unsigned bu = __shfl_sync(FULL, wBu, src);
            a[i] = 0.f;
            if ((okmask >> src) & 1u) {
                __half2 pa = *reinterpret_cast<__half2*>(&au);
                __half2 pb = *reinterpret_cast<__half2*>(&bu);
                __half2 W00 = __low2half2(pa);
                __half2 W01 = __high2half2(pa);
                __half2 W10 = __low2half2(pb);
                __half2 W11 = __high2half2(pb);
                const char* p00 = lbase + offi;
                float4 A = *reinterpret_cast<const float4*>(p00);
                float4 Bc = *reinterpret_cast<const float4*>(p00 + kTEXB);
                float4 Cc = *reinterpret_cast<const float4*>(p00 + kW * kTEXB);
                float4 Dc = *reinterpret_cast<const float4*>(p00 + kW * kTEXB + kTEXB);
                const __half2* Ah = reinterpret_cast<const __half2*>(&A);
                const __half2* Bh = reinterpret_cast<const __half2*>(&Bc);
                const __half2* Ch = reinterpret_cast<const __half2*>(&Cc);
                const __half2* Dh = reinterpret_cast<const __half2*>(&Dc);
                __half2 acc2 = __float2half2_rn(0.f);
#pragma unroll
                for (int k = 0; k < 4; k++) {
                    __half2 val = __hfma2(Ah[k], W00,
                                  __hfma2(Bh[k], W01,
                                  __hfma2(Ch[k], W10,
                                  __hmul2(Dh[k], W11))));
                    acc2 = __hadd2(acc2, __habs2(__hsub2(val, curh[k])));
                }
                float2 f = __half22float2(acc2);
                a[i] = f.x + f.y;
            }
        }

        // 8x8 transpose-reduction: lane q ends with the full 8-lane sum of
        // its own depth's a[q]. 7 shfls total, static register indices.
        float b4[4];
#pragma unroll
        for (int k = 0; k < 4; k++) {
            float send = (q & 4) ? a[k] : a[k + 4];
            float rcv = __shfl_xor_sync(FULL, send, 4);
            b4[k] = ((q & 4) ? a[k + 4] : a[k]) + rcv;
        }
        float c2[2];
#pragma unroll
        for (int j = 0; j < 2; j++) {
            float send = (q & 2) ? b4[j] : b4[j + 2];
            float rcv = __shfl_xor_sync(FULL, send, 2);
            c2[j] = ((q & 2) ? b4[j + 2] : b4[j]) + rcv;
        }
        {
            float send = (q & 1) ? c2[0] : c2[1];
            float rcv = __shfl_xor_sync(FULL, send, 1);
            mydiff = (((q & 1) ? c2[1] : c2[0]) + rcv) * (1.f / (float)kC);
        }
    }

    // cost / missing / max-over-depth (lane = depth)
    float cnt = (mydiff > 0.f) ? 1.f : 0.f;
    float cost = mydiff / (cnt + 1e-7f);
    float miss = (mydiff == 0.f) ? 1.f : 0.f;
    float maxv = cost;
#pragma unroll
    for (int o = 16; o > 0; o >>= 1)
        maxv = fmaxf(maxv, __shfl_xor_sync(FULL, maxv, o));
    float outc = (miss != 0.f) ? maxv : cost;

    cost_s[lane][wp] = outc;
    miss_s[lane][wp] = miss;
    __syncthreads();

    // coalesced stores: 8 consecutive w per depth row
    const int d = tid >> 3, p = tid & 7;
    size_t oidx = (((size_t)b * kD + d) * kH + h) * kW + (w0 + p);
    out[oidx] = cost_s[d][p];
    out[kBDHW + oidx] = miss_s[d][p];
}

extern "C" void kernel_launch(void* const* d_in, const int* in_sizes, int n_in,
                              void* d_out, int out_size) {
    const float* cur    = (const float*)d_in[0];  // current_feats [B,C,H,W]
    const float* lookup = (const float*)d_in[1];  // lookup_feats  [B,1,C,H,W]
    const float* prior  = (const float*)d_in[2];  // prior_depth   [B,1,H,W]
    const float* sfac   = (const float*)d_in[3];  // scale_facs    [H,W]
    const float* theta  = (const float*)d_in[4];  // theta_lut     [B,H,W]
    const float* angle  = (const float*)d_in[5];  // angle_lut     [B,H,W]
    const float* pose   = (const float*)d_in[6];  // lookup_poses  [B,1,4,4]
    const float* intr   = (const float*)d_in[7];  // intrinsics    [B,3,3]
    const float* dist   = (const float*)d_in[8];  // distortion    [B,4]
    float* out = (float*)d_out;                   // [2, B, D, H, W]

    dim3 pgrid(kHW / PACK_PIX, kB);               // (102, 2)
    pack_kernel<<<pgrid, 256>>>(lookup);

    cv_kernel<<<kNPIX / 8, 256>>>(cur, prior, sfac, theta, angle, pose,
                                  intr, dist, out);
}